// round 4
// baseline (speedup 1.0000x reference)
#include <cuda_runtime.h>

#define BATCH 4
#define CDIM 256
#define NTOK 4096   // 64*64
#define TCD 768     // 3*C
#define FULLMASK 0xffffffffu

// Scratch (allocation-free rule: __device__ globals)
__device__ float g_Q[BATCH * NTOK * CDIM];
__device__ float g_K[BATCH * NTOK * CDIM];
__device__ float g_V[BATCH * NTOK * CDIM];
__device__ float g_AO[BATCH * NTOK * CDIM];

__device__ __forceinline__ unsigned to_tf32_bits(float x) {
    unsigned r;
    asm("cvt.rna.tf32.f32 %0, %1;" : "=r"(r) : "f"(x));
    return r;
}
__device__ __forceinline__ float to_tf32(float x) {
    return __uint_as_float(to_tf32_bits(x));
}
__device__ __forceinline__ float ex2(float x) {
    float r;
    asm("ex2.approx.f32 %0, %1;" : "=f"(r) : "f"(x));
    return r;
}
__device__ __forceinline__ void mma_tf32(float d[4], const unsigned a[4], const unsigned b[2]) {
    asm volatile(
        "mma.sync.aligned.m16n8k8.row.col.f32.tf32.tf32.f32 "
        "{%0,%1,%2,%3}, {%4,%5,%6,%7}, {%8,%9}, {%0,%1,%2,%3};\n"
        : "+f"(d[0]), "+f"(d[1]), "+f"(d[2]), "+f"(d[3])
        : "r"(a[0]), "r"(a[1]), "r"(a[2]), "r"(a[3]), "r"(b[0]), "r"(b[1]));
}

// ---------------------------------------------------------------------------
// Kernel 1: QKV GEMM via tf32 mma.  C[n][d] = sum_c x[b,c,n] * Wqkv[d,c].
// x chunk stored natively [c][n] (A-frags read transposed, conflict-free).
// grid (32, 12, 4), 256 threads. Warp tile 64n x 16d. Double-buffered.
// ---------------------------------------------------------------------------
#define XS 132
#define WS 36
#define QKV_SMEM ((2 * (32 * XS + 64 * WS)) * 4)

__global__ __launch_bounds__(256) void qkv_kernel(const float* __restrict__ x,
                                                  const float* __restrict__ Wqkv) {
    extern __shared__ float sq[];
    float* Xs[2] = {sq, sq + 32 * XS + 64 * WS};
    float* Wsm[2] = {sq + 32 * XS, sq + 2 * 32 * XS + 64 * WS};

    const int b  = blockIdx.z;
    const int n0 = blockIdx.x * 128;
    const int d0 = blockIdx.y * 64;
    const int tid = threadIdx.x;
    const int lane = tid & 31, w = tid >> 5;
    const int g = lane >> 2, t = lane & 3;
    const int wm = w >> 2, wn = w & 3;        // 2 x 4 warp grid

    const float* xb = x + (long)b * CDIM * NTOK;

    float acc[4][2][4] = {};

    // prologue: load chunk 0
    {
#pragma unroll
        for (int tl = 0; tl < 4; tl++) {   // X: 32c x 128n = 1024 f4
            const int f4 = tid + tl * 256;
            const int row = f4 >> 5, cq = f4 & 31;
            *(float4*)&Xs[0][row * XS + cq * 4] =
                *(const float4*)&xb[(long)row * NTOK + n0 + cq * 4];
        }
#pragma unroll
        for (int tl = 0; tl < 2; tl++) {   // W: 64d x 32c = 512 f4
            const int f4 = tid + tl * 256;
            const int row = f4 >> 3, cq = f4 & 7;
            *(float4*)&Wsm[0][row * WS + cq * 4] =
                *(const float4*)&Wqkv[(long)(d0 + row) * CDIM + cq * 4];
        }
    }
    __syncthreads();

    for (int ck = 0; ck < 8; ck++) {
        const int cur = ck & 1;
        if (ck < 7) {
            const int c0 = (ck + 1) * 32;
            const int nxt = cur ^ 1;
#pragma unroll
            for (int tl = 0; tl < 4; tl++) {
                const int f4 = tid + tl * 256;
                const int row = f4 >> 5, cq = f4 & 31;
                *(float4*)&Xs[nxt][row * XS + cq * 4] =
                    *(const float4*)&xb[(long)(c0 + row) * NTOK + n0 + cq * 4];
            }
#pragma unroll
            for (int tl = 0; tl < 2; tl++) {
                const int f4 = tid + tl * 256;
                const int row = f4 >> 3, cq = f4 & 7;
                *(float4*)&Wsm[nxt][row * WS + cq * 4] =
                    *(const float4*)&Wqkv[(long)(d0 + row) * CDIM + c0 + cq * 4];
            }
        }
#pragma unroll
        for (int ks = 0; ks < 4; ks++) {
            const int k = ks * 8;
            unsigned a[4][4], bb[2][2];
#pragma unroll
            for (int mt = 0; mt < 4; mt++) {
                const int nb = wm * 64 + mt * 16 + g;
                a[mt][0] = __float_as_uint(Xs[cur][(k + t) * XS + nb]);
                a[mt][1] = __float_as_uint(Xs[cur][(k + t) * XS + nb + 8]);
                a[mt][2] = __float_as_uint(Xs[cur][(k + t + 4) * XS + nb]);
                a[mt][3] = __float_as_uint(Xs[cur][(k + t + 4) * XS + nb + 8]);
            }
#pragma unroll
            for (int nt = 0; nt < 2; nt++) {
                const float* wr = &Wsm[cur][(wn * 16 + nt * 8 + g) * WS + k + t];
                bb[nt][0] = __float_as_uint(wr[0]);
                bb[nt][1] = __float_as_uint(wr[4]);
            }
#pragma unroll
            for (int mt = 0; mt < 4; mt++)
#pragma unroll
                for (int nt = 0; nt < 2; nt++)
                    mma_tf32(acc[mt][nt], a[mt], bb[nt]);
        }
        __syncthreads();
    }

    const int seg = d0 >> 8;
    float* base = (seg == 0) ? g_Q : (seg == 1) ? g_K : g_V;
    const int dlocal0 = (d0 & 255);
#pragma unroll
    for (int mt = 0; mt < 4; mt++) {
        const int n = n0 + wm * 64 + mt * 16 + g;
#pragma unroll
        for (int nt = 0; nt < 2; nt++) {
            const int col = dlocal0 + wn * 16 + nt * 8 + 2 * t;
            *(float2*)&base[((long)b * NTOK + n) * CDIM + col] =
                make_float2(to_tf32(acc[mt][nt][0]), to_tf32(acc[mt][nt][1]));
            *(float2*)&base[((long)b * NTOK + n + 8) * CDIM + col] =
                make_float2(to_tf32(acc[mt][nt][2]), to_tf32(acc[mt][nt][3]));
        }
    }
}

// ---------------------------------------------------------------------------
// Kernel 2: tf32 mma flash attention, Q resident, register-P (no smem P).
// grid (32, 4), 256 threads, 8 warps; warp owns 16 query rows x all 128 keys.
// ---------------------------------------------------------------------------
#define QSTR 260
#define KSTR 68
#define VSTR 260
#define KVBUF 8704   // max(128*68, 32*260)
#define ATTN_SMEM ((128 * QSTR + 2 * KVBUF + 128) * 4)

__global__ __launch_bounds__(256) void attn_kernel(const int* __restrict__ fg_mask) {
    extern __shared__ float sm[];
    float* Qs  = sm;                   // [128][260]
    float* KV0 = Qs + 128 * QSTR;
    float* KV1 = KV0 + KVBUF;
    float* fgf = KV1 + KVBUF;          // [128]

    const int b  = blockIdx.y;
    const int q0 = blockIdx.x * 128;
    const int tid = threadIdx.x;
    const int lane = tid & 31, w = tid >> 5;
    const int g = lane >> 2, t = lane & 3;
    const int qrow = w * 16 + g;

    const float* Qg = g_Q + ((long)b * NTOK + q0) * CDIM;
    const float* Kg = g_K + (long)b * NTOK * CDIM;
    const float* Vg = g_V + (long)b * NTOK * CDIM;

    // resident Q tile [128 n][256 c]
#pragma unroll
    for (int tl = 0; tl < 32; tl++) {
        const int f4 = tid + tl * 256;
        const int row = f4 >> 6, cq = f4 & 63;
        *(float4*)&Qs[row * QSTR + cq * 4] =
            *(const float4*)&Qg[(long)row * CDIM + cq * 4];
    }

    float oacc[32][4];
#pragma unroll
    for (int i = 0; i < 32; i++)
#pragma unroll
        for (int j = 0; j < 4; j++) oacc[i][j] = 0.0f;
    float l0 = 0.0f, l1 = 0.0f;

    const float SC = 0.0625f * 1.4426950408889634f;   // 1/sqrt(C) * log2(e)

    for (int m0 = 0; m0 < NTOK; m0 += 128) {
        if (tid < 128) fgf[tid] = fg_mask[b * NTOK + m0 + tid] ? 1.0f : 0.0f;
        // K chunk 0 (c 0..63) -> KV0
#pragma unroll
        for (int tl = 0; tl < 8; tl++) {
            const int f4 = tid + tl * 256;
            const int row = f4 >> 4, cq = f4 & 15;
            *(float4*)&KV0[row * KSTR + cq * 4] =
                *(const float4*)&Kg[(long)(m0 + row) * CDIM + cq * 4];
        }
        __syncthreads();   // also covers Q visibility on first tile

        float sacc[16][4];
#pragma unroll
        for (int i = 0; i < 16; i++)
#pragma unroll
            for (int j = 0; j < 4; j++) sacc[i][j] = 0.0f;

        // ---- S phase: 4 c-chunks of 64, double-buffered ----
        for (int cc = 0; cc < 4; cc++) {
            float* cur = (cc & 1) ? KV1 : KV0;
            if (cc < 3) {
                float* nxt = (cc & 1) ? KV0 : KV1;
                const int c0 = (cc + 1) * 64;
#pragma unroll
                for (int tl = 0; tl < 8; tl++) {
                    const int f4 = tid + tl * 256;
                    const int row = f4 >> 4, cq = f4 & 15;
                    *(float4*)&nxt[row * KSTR + cq * 4] =
                        *(const float4*)&Kg[(long)(m0 + row) * CDIM + c0 + cq * 4];
                }
            }
            const int c0q = cc * 64;
#pragma unroll
            for (int ks = 0; ks < 8; ks++) {
                const int k = ks * 8;
                unsigned a[4];
                const float* qr = &Qs[qrow * QSTR + c0q + k + t];
                a[0] = __float_as_uint(qr[0]);
                a[1] = __float_as_uint(qr[8 * QSTR]);
                a[2] = __float_as_uint(qr[4]);
                a[3] = __float_as_uint(qr[8 * QSTR + 4]);
#pragma unroll
                for (int nt = 0; nt < 16; nt++) {
                    unsigned bb[2];
                    const float* kr = &cur[(nt * 8 + g) * KSTR + k + t];
                    bb[0] = __float_as_uint(kr[0]);
                    bb[1] = __float_as_uint(kr[4]);
                    mma_tf32(sacc[nt], a, bb);
                }
            }
            __syncthreads();
        }

        // ---- softmax: mask * exp2(S*SC), tf32-round, in-register row sums ----
        float rs0 = 0.0f, rs1 = 0.0f;
#pragma unroll
        for (int nt = 0; nt < 16; nt++) {
            float2 f = *(const float2*)&fgf[nt * 8 + 2 * t];
            float p0 = to_tf32(ex2(sacc[nt][0] * SC) * f.x);
            float p1 = to_tf32(ex2(sacc[nt][1] * SC) * f.y);
            float p2 = to_tf32(ex2(sacc[nt][2] * SC) * f.x);
            float p3 = to_tf32(ex2(sacc[nt][3] * SC) * f.y);
            sacc[nt][0] = p0; sacc[nt][1] = p1; sacc[nt][2] = p2; sacc[nt][3] = p3;
            rs0 += p0 + p1;
            rs1 += p2 + p3;
        }
        rs0 += __shfl_xor_sync(FULLMASK, rs0, 1);
        rs0 += __shfl_xor_sync(FULLMASK, rs0, 2);
        rs1 += __shfl_xor_sync(FULLMASK, rs1, 1);
        rs1 += __shfl_xor_sync(FULLMASK, rs1, 2);
        l0 += rs0;
        l1 += rs1;

        // ---- PV phase: 4 key-chunks of 32 (full 256 c), double-buffered ----
        // V chunk 0 -> KV0 (both buffers free after S-phase final sync)
#pragma unroll
        for (int tl = 0; tl < 8; tl++) {
            const int f4 = tid + tl * 256;
            const int row = f4 >> 6, cq = f4 & 63;
            *(float4*)&KV0[row * VSTR + cq * 4] =
                *(const float4*)&Vg[(long)(m0 + row) * CDIM + cq * 4];
        }
        __syncthreads();

        for (int kc = 0; kc < 4; kc++) {
            float* cur = (kc & 1) ? KV1 : KV0;
            if (kc < 3) {
                float* nxt = (kc & 1) ? KV0 : KV1;
                const int kb = (kc + 1) * 32;
#pragma unroll
                for (int tl = 0; tl < 8; tl++) {
                    const int f4 = tid + tl * 256;
                    const int row = f4 >> 6, cq = f4 & 63;
                    *(float4*)&nxt[row * VSTR + cq * 4] =
                        *(const float4*)&Vg[(long)(m0 + kb + row) * CDIM + cq * 4];
                }
            }
#pragma unroll
            for (int ks = 0; ks < 4; ks++) {
                const int j = kc * 4 + ks;   // P col-group
                // register transpose: accumulator layout -> A-operand layout
                const unsigned srcA = (lane & ~3u) | (unsigned)(t >> 1);
                float q0A = __shfl_sync(FULLMASK, sacc[j][0], srcA);
                float q1A = __shfl_sync(FULLMASK, sacc[j][1], srcA);
                float q2A = __shfl_sync(FULLMASK, sacc[j][2], srcA);
                float q3A = __shfl_sync(FULLMASK, sacc[j][3], srcA);
                float q0B = __shfl_sync(FULLMASK, sacc[j][0], srcA + 2);
                float q1B = __shfl_sync(FULLMASK, sacc[j][1], srcA + 2);
                float q2B = __shfl_sync(FULLMASK, sacc[j][2], srcA + 2);
                float q3B = __shfl_sync(FULLMASK, sacc[j][3], srcA + 2);
                unsigned a[4];
                a[0] = __float_as_uint((t & 1) ? q1A : q0A);   // P[g][t]
                a[1] = __float_as_uint((t & 1) ? q3A : q2A);   // P[g+8][t]
                a[2] = __float_as_uint((t & 1) ? q1B : q0B);   // P[g][t+4]
                a[3] = __float_as_uint((t & 1) ? q3B : q2B);   // P[g+8][t+4]
#pragma unroll
                for (int nt = 0; nt < 32; nt++) {
                    unsigned bb[2];
                    bb[0] = __float_as_uint(cur[(ks * 8 + t) * VSTR + nt * 8 + g]);
                    bb[1] = __float_as_uint(cur[(ks * 8 + t + 4) * VSTR + nt * 8 + g]);
                    mma_tf32(oacc[nt], a, bb);
                }
            }
            __syncthreads();
        }
    }

    // ---- epilogue: normalize + store ----
    float* AOg = g_AO + ((long)b * NTOK + q0) * CDIM;
    const float inv0 = 1.0f / l0;
    const float inv1 = 1.0f / l1;
#pragma unroll
    for (int nt = 0; nt < 32; nt++) {
        const int col = nt * 8 + 2 * t;
        *(float2*)&AOg[(long)qrow * CDIM + col] =
            make_float2(oacc[nt][0] * inv0, oacc[nt][1] * inv0);
        *(float2*)&AOg[(long)(qrow + 8) * CDIM + col] =
            make_float2(oacc[nt][2] * inv1, oacc[nt][3] * inv1);
    }
}

// ---------------------------------------------------------------------------
// Kernel 3: projection via tf32 mma + bias + smem transpose store.
// out[b][d][n] = sum_c AO[b][n][c] * Wp[d][c] + bp[d]
// grid (32, 4, 4), 256 threads. Warp tile 64n x 16d.
// ---------------------------------------------------------------------------
#define AS 36
#define CS 132
#define PROJ_SMEM ((2 * (128 * AS + 64 * AS)) * 4)   // Cs (64*132) overlays

__global__ __launch_bounds__(256) void proj_kernel(const float* __restrict__ Wp,
                                                   const float* __restrict__ bp,
                                                   float* __restrict__ out) {
    extern __shared__ float sp[];
    float* As[2] = {sp, sp + 128 * AS + 64 * AS};
    float* Wsm[2] = {sp + 128 * AS, sp + 2 * 128 * AS + 64 * AS};
    float* Cs = sp;   // overlay after GEMM

    const int b   = blockIdx.z;
    const int n0  = blockIdx.x * 128;
    const int co0 = blockIdx.y * 64;
    const int tid = threadIdx.x;
    const int lane = tid & 31, w = tid >> 5;
    const int g = lane >> 2, t = lane & 3;
    const int wm = w >> 2, wn = w & 3;

    const float* A = g_AO + ((long)b * NTOK + n0) * CDIM;

    float acc[4][2][4] = {};

    // prologue chunk 0
    {
#pragma unroll
        for (int tl = 0; tl < 4; tl++) {   // A: 128n x 32c = 1024 f4
            const int f4 = tid + tl * 256;
            const int row = f4 >> 3, cq = f4 & 7;
            *(float4*)&As[0][row * AS + cq * 4] =
                *(const float4*)&A[(long)row * CDIM + cq * 4];
        }
#pragma unroll
        for (int tl = 0; tl < 2; tl++) {   // W: 64d x 32c
            const int f4 = tid + tl * 256;
            const int row = f4 >> 3, cq = f4 & 7;
            *(float4*)&Wsm[0][row * AS + cq * 4] =
                *(const float4*)&Wp[(long)(co0 + row) * CDIM + cq * 4];
        }
    }
    __syncthreads();

    for (int ck = 0; ck < 8; ck++) {
        const int cur = ck & 1;
        if (ck < 7) {
            const int c0 = (ck + 1) * 32;
            const int nxt = cur ^ 1;
#pragma unroll
            for (int tl = 0; tl < 4; tl++) {
                const int f4 = tid + tl * 256;
                const int row = f4 >> 3, cq = f4 & 7;
                *(float4*)&As[nxt][row * AS + cq * 4] =
                    *(const float4*)&A[(long)row * CDIM + c0 + cq * 4];
            }
#pragma unroll
            for (int tl = 0; tl < 2; tl++) {
                const int f4 = tid + tl * 256;
                const int row = f4 >> 3, cq = f4 & 7;
                *(float4*)&Wsm[nxt][row * AS + cq * 4] =
                    *(const float4*)&Wp[(long)(co0 + row) * CDIM + c0 + cq * 4];
            }
        }
#pragma unroll
        for (int ks = 0; ks < 4; ks++) {
            const int k = ks * 8;
            unsigned a[4][4], bb[2][2];
#pragma unroll
            for (int mt = 0; mt < 4; mt++) {
                const float* ar = &As[cur][(wm * 64 + mt * 16 + g) * AS + k + t];
                a[mt][0] = __float_as_uint(ar[0]);
                a[mt][1] = __float_as_uint(ar[8 * AS]);
                a[mt][2] = __float_as_uint(ar[4]);
                a[mt][3] = __float_as_uint(ar[8 * AS + 4]);
            }
#pragma unroll
            for (int nt = 0; nt < 2; nt++) {
                const float* wr = &Wsm[cur][(wn * 16 + nt * 8 + g) * AS + k + t];
                bb[nt][0] = __float_as_uint(wr[0]);
                bb[nt][1] = __float_as_uint(wr[4]);
            }
#pragma unroll
            for (int mt = 0; mt < 4; mt++)
#pragma unroll
                for (int nt = 0; nt < 2; nt++)
                    mma_tf32(acc[mt][nt], a[mt], bb[nt]);
        }
        __syncthreads();
    }

    // stage transposed into Cs[d][n]
#pragma unroll
    for (int mt = 0; mt < 4; mt++) {
        const int n = wm * 64 + mt * 16 + g;
#pragma unroll
        for (int nt = 0; nt < 2; nt++) {
            const int col = wn * 16 + nt * 8 + 2 * t;
            Cs[(col) * CS + n]         = acc[mt][nt][0];
            Cs[(col + 1) * CS + n]     = acc[mt][nt][1];
            Cs[(col) * CS + n + 8]     = acc[mt][nt][2];
            Cs[(col + 1) * CS + n + 8] = acc[mt][nt][3];
        }
    }
    __syncthreads();

    // coalesced store out[b][co0+d][n0..n0+128) with bias
#pragma unroll
    for (int tl = 0; tl < 8; tl++) {
        const int f4 = tid + tl * 256;
        const int row = f4 >> 5, cq = f4 & 31;
        const float bias = bp[co0 + row];
        float4 v = *(const float4*)&Cs[row * CS + cq * 4];
        v.x += bias; v.y += bias; v.z += bias; v.w += bias;
        *(float4*)&out[((long)b * CDIM + co0 + row) * NTOK + n0 + cq * 4] = v;
    }
}

// ---------------------------------------------------------------------------
extern "C" void kernel_launch(void* const* d_in, const int* in_sizes, int n_in,
                              void* d_out, int out_size) {
    const float* x    = (const float*)d_in[0];
    const int*   fg   = (const int*)d_in[1];
    const float* Wqkv = (const float*)d_in[2];
    const float* Wp   = (const float*)d_in[3];
    const float* bp   = (const float*)d_in[4];
    float* out = (float*)d_out;

    cudaFuncSetAttribute(qkv_kernel, cudaFuncAttributeMaxDynamicSharedMemorySize, QKV_SMEM);
    cudaFuncSetAttribute(attn_kernel, cudaFuncAttributeMaxDynamicSharedMemorySize, ATTN_SMEM);
    cudaFuncSetAttribute(proj_kernel, cudaFuncAttributeMaxDynamicSharedMemorySize, PROJ_SMEM);

    qkv_kernel<<<dim3(NTOK / 128, TCD / 64, BATCH), 256, QKV_SMEM>>>(x, Wqkv);
    attn_kernel<<<dim3(NTOK / 128, BATCH), 256, ATTN_SMEM>>>(fg);
    proj_kernel<<<dim3(NTOK / 128, CDIM / 64, BATCH), 256, PROJ_SMEM>>>(Wp, bp, out);
}